// round 2
// baseline (speedup 1.0000x reference)
#include <cuda_runtime.h>

#define N_NODES 100000
#define D 128
#define N_EDGES 400000
#define BN_EPS 1e-5f

#define GEMM_WARPS 8
#define TM 8            // rows per warp
#define WPAD 132        // padded row (words) for transposed W in smem

// Scratch (allocation-free rule: device globals only)
__device__ float g_sum[D];
__device__ float g_sumsq[D];
__device__ float g_scale[D];
__device__ float g_shift[D];
__device__ float g_h[(size_t)N_NODES * D];

// CSR build scratch
__device__ int   g_cnt[N_NODES];       // per-row edge count
__device__ int   g_off[N_NODES + 1];   // exclusive offsets
__device__ int   g_cur[N_NODES];       // scatter cursors
__device__ int   g_scol[N_EDGES];      // row-sorted col indices
__device__ float g_sw[N_EDGES];        // row-sorted weights

// ---------------------------------------------------------------------------
// K0: zero stat accumulators + histogram counters (graph replays => every call)
// ---------------------------------------------------------------------------
__global__ void k_zero_all() {
    int idx = blockIdx.x * blockDim.x + threadIdx.x;
    for (int i = idx; i < N_NODES; i += gridDim.x * blockDim.x) g_cnt[i] = 0;
    if (idx < D) { g_sum[idx] = 0.f; g_sumsq[idx] = 0.f; }
}

// ---------------------------------------------------------------------------
// K1: per-column sum / sumsq
// ---------------------------------------------------------------------------
__global__ void k_colsum(const float* __restrict__ x) {
    int c = threadIdx.x;
    float s = 0.f, s2 = 0.f;
#pragma unroll 4
    for (int r = blockIdx.x; r < N_NODES; r += gridDim.x) {
        float v = x[(size_t)r * D + c];
        s += v;
        s2 += v * v;
    }
    atomicAdd(&g_sum[c], s);
    atomicAdd(&g_sumsq[c], s2);
}

// ---------------------------------------------------------------------------
// K1b: histogram of destination rows
// ---------------------------------------------------------------------------
__global__ void k_hist(const int* __restrict__ eidx) {
    int e = blockIdx.x * blockDim.x + threadIdx.x;
    if (e < N_EDGES) atomicAdd(&g_cnt[eidx[e]], 1);
}

// ---------------------------------------------------------------------------
// K2: fold BN into per-column scale/shift
// ---------------------------------------------------------------------------
__global__ void k_stats(const float* __restrict__ gamma, const float* __restrict__ beta) {
    int c = threadIdx.x;
    const float inv_n = 1.f / (float)N_NODES;
    float mu = g_sum[c] * inv_n;
    float var = g_sumsq[c] * inv_n - mu * mu;
    float rs = rsqrtf(var + BN_EPS);
    float sc = gamma[c] * rs;
    g_scale[c] = sc;
    g_shift[c] = beta[c] - mu * sc;
}

// ---------------------------------------------------------------------------
// K2b: single-block exclusive scan of g_cnt -> g_off (and init cursors)
// ---------------------------------------------------------------------------
__global__ void k_scan() {
    __shared__ int partial[1024];
    const int TOT = N_NODES + 1;
    const int CH = (TOT + 1023) / 1024;
    int t = threadIdx.x;
    int base = t * CH;

    int s = 0;
    for (int i = 0; i < CH; i++) {
        int idx = base + i;
        if (idx < N_NODES) s += g_cnt[idx];
    }
    partial[t] = s;
    __syncthreads();
    // Hillis-Steele inclusive scan
    for (int off = 1; off < 1024; off <<= 1) {
        int v = (t >= off) ? partial[t - off] : 0;
        __syncthreads();
        partial[t] += v;
        __syncthreads();
    }
    int run = (t == 0) ? 0 : partial[t - 1];
    for (int i = 0; i < CH; i++) {
        int idx = base + i;
        if (idx <= N_NODES) {
            int c = (idx < N_NODES) ? g_cnt[idx] : 0;
            g_off[idx] = run;
            if (idx < N_NODES) g_cur[idx] = run;
            run += c;
        }
    }
}

// ---------------------------------------------------------------------------
// K2c: scatter edges into row-sorted CSR arrays
// ---------------------------------------------------------------------------
__global__ void k_scatter(const int* __restrict__ eidx, const float* __restrict__ ew) {
    int e = blockIdx.x * blockDim.x + threadIdx.x;
    if (e >= N_EDGES) return;
    int r = eidx[e];
    int c = eidx[N_EDGES + e];
    int pos = atomicAdd(&g_cur[r], 1);
    g_scol[pos] = c;
    g_sw[pos] = ew[e];
}

// ---------------------------------------------------------------------------
// K3: fused BN -> ReLU -> GEMM (h = y @ W^T), writes g_h and out = h*h.
// ---------------------------------------------------------------------------
extern __shared__ float sm_gemm[];

__global__ void __launch_bounds__(256, 2) k_gemm(const float* __restrict__ x,
                                                 const float* __restrict__ W,
                                                 float* __restrict__ out) {
    float* Wsh = sm_gemm;                       // D * WPAD
    float* ysh = Wsh + D * WPAD;                // GEMM_WARPS * TM * D
    float* ssc = ysh + GEMM_WARPS * TM * D;     // D
    float* ssh = ssc + D;                       // D

    int tid = threadIdx.x;

    for (int i = tid; i < D * D; i += blockDim.x) {
        int j = i / D;
        int k = i - j * D;
        Wsh[k * WPAD + j] = W[i];
    }
    if (tid < D) {
        ssc[tid] = g_scale[tid];
        ssh[tid] = g_shift[tid];
    }
    __syncthreads();

    int warp = tid >> 5;
    int lane = tid & 31;
    float* myY = ysh + warp * TM * D;

    float sc[4], sh[4];
#pragma unroll
    for (int i = 0; i < 4; i++) {
        sc[i] = ssc[4 * lane + i];
        sh[i] = ssh[4 * lane + i];
    }

    const int ntiles = (N_NODES + GEMM_WARPS * TM - 1) / (GEMM_WARPS * TM);
    for (int tile = blockIdx.x; tile < ntiles; tile += gridDim.x) {
        int row0 = tile * (GEMM_WARPS * TM) + warp * TM;

        __syncwarp();
#pragma unroll
        for (int r = 0; r < TM; r++) {
            int row = row0 + r;
            if (row < N_NODES) {
                float4 v = *(const float4*)&x[(size_t)row * D + 4 * lane];
                v.x = fmaxf(0.f, fmaf(v.x, sc[0], sh[0]));
                v.y = fmaxf(0.f, fmaf(v.y, sc[1], sh[1]));
                v.z = fmaxf(0.f, fmaf(v.z, sc[2], sh[2]));
                v.w = fmaxf(0.f, fmaf(v.w, sc[3], sh[3]));
                *(float4*)&myY[r * D + 4 * lane] = v;
            }
        }
        __syncwarp();

        unsigned long long acc[TM][2];
#pragma unroll
        for (int r = 0; r < TM; r++) { acc[r][0] = 0ULL; acc[r][1] = 0ULL; }

#pragma unroll 8
        for (int k = 0; k < D; k++) {
            float4 w4 = *(const float4*)&Wsh[k * WPAD + 4 * lane];
            unsigned long long w01, w23;
            asm("mov.b64 %0, {%1,%2};" : "=l"(w01) : "f"(w4.x), "f"(w4.y));
            asm("mov.b64 %0, {%1,%2};" : "=l"(w23) : "f"(w4.z), "f"(w4.w));
#pragma unroll
            for (int r = 0; r < TM; r++) {
                float yv = myY[r * D + k];
                unsigned long long yy;
                asm("mov.b64 %0, {%1,%1};" : "=l"(yy) : "f"(yv));
                asm("fma.rn.f32x2 %0, %1, %2, %0;" : "+l"(acc[r][0]) : "l"(yy), "l"(w01));
                asm("fma.rn.f32x2 %0, %1, %2, %0;" : "+l"(acc[r][1]) : "l"(yy), "l"(w23));
            }
        }

#pragma unroll
        for (int r = 0; r < TM; r++) {
            int row = row0 + r;
            if (row < N_NODES) {
                float4 hv;
                asm("mov.b64 {%0,%1}, %2;" : "=f"(hv.x), "=f"(hv.y) : "l"(acc[r][0]));
                asm("mov.b64 {%0,%1}, %2;" : "=f"(hv.z), "=f"(hv.w) : "l"(acc[r][1]));
                *(float4*)&g_h[(size_t)row * D + 4 * lane] = hv;
                float4 o = make_float4(hv.x * hv.x, hv.y * hv.y, hv.z * hv.z, hv.w * hv.w);
                *(float4*)&out[(size_t)row * D + 4 * lane] = o;
            }
        }
    }
}

// ---------------------------------------------------------------------------
// K4: CSR aggregation. One warp per node, lanes cover 128 features (4 each).
// No atomics: out[n] += sum_j w_j * h[col_j].
// ---------------------------------------------------------------------------
__global__ void k_agg(float* __restrict__ out) {
    int warp_global = (int)((blockIdx.x * (unsigned)blockDim.x + threadIdx.x) >> 5);
    int lane = threadIdx.x & 31;
    if (warp_global >= N_NODES) return;
    int n = warp_global;
    int s = g_off[n];
    int e = g_off[n + 1];
    if (s == e) return;   // out already holds h*h

    float4 acc0 = make_float4(0.f, 0.f, 0.f, 0.f);
    float4 acc1 = make_float4(0.f, 0.f, 0.f, 0.f);

    int j = s;
    for (; j + 1 < e; j += 2) {
        int c0 = g_scol[j];
        int c1 = g_scol[j + 1];
        float w0 = g_sw[j];
        float w1 = g_sw[j + 1];
        float4 v0 = *(const float4*)&g_h[(size_t)c0 * D + 4 * lane];
        float4 v1 = *(const float4*)&g_h[(size_t)c1 * D + 4 * lane];
        acc0.x = fmaf(w0, v0.x, acc0.x); acc0.y = fmaf(w0, v0.y, acc0.y);
        acc0.z = fmaf(w0, v0.z, acc0.z); acc0.w = fmaf(w0, v0.w, acc0.w);
        acc1.x = fmaf(w1, v1.x, acc1.x); acc1.y = fmaf(w1, v1.y, acc1.y);
        acc1.z = fmaf(w1, v1.z, acc1.z); acc1.w = fmaf(w1, v1.w, acc1.w);
    }
    if (j < e) {
        int c0 = g_scol[j];
        float w0 = g_sw[j];
        float4 v0 = *(const float4*)&g_h[(size_t)c0 * D + 4 * lane];
        acc0.x = fmaf(w0, v0.x, acc0.x); acc0.y = fmaf(w0, v0.y, acc0.y);
        acc0.z = fmaf(w0, v0.z, acc0.z); acc0.w = fmaf(w0, v0.w, acc0.w);
    }
    acc0.x += acc1.x; acc0.y += acc1.y; acc0.z += acc1.z; acc0.w += acc1.w;

    float4* dst = (float4*)&out[(size_t)n * D + 4 * lane];
    float4 o = *dst;
    o.x += acc0.x; o.y += acc0.y; o.z += acc0.z; o.w += acc0.w;
    *dst = o;
}

// ---------------------------------------------------------------------------
extern "C" void kernel_launch(void* const* d_in, const int* in_sizes, int n_in,
                              void* d_out, int out_size) {
    const float* x     = (const float*)d_in[0];
    const int*   eidx  = (const int*)d_in[1];
    const float* ew    = (const float*)d_in[2];
    const float* gamma = (const float*)d_in[3];
    const float* beta  = (const float*)d_in[4];
    const float* W     = (const float*)d_in[5];
    float* out = (float*)d_out;

    k_zero_all<<<200, 512>>>();
    k_colsum<<<464, D>>>(x);
    k_hist<<<(N_EDGES + 255) / 256, 256>>>(eidx);
    k_stats<<<1, D>>>(gamma, beta);
    k_scan<<<1, 1024>>>();
    k_scatter<<<(N_EDGES + 255) / 256, 256>>>(eidx, ew);

    const size_t smem = (size_t)(D * WPAD + GEMM_WARPS * TM * D + 2 * D) * sizeof(float);
    cudaFuncSetAttribute(k_gemm, cudaFuncAttributeMaxDynamicSharedMemorySize, (int)smem);
    k_gemm<<<304, 256, smem>>>(x, W, out);

    k_agg<<<(N_NODES * 32 + 255) / 256, 256>>>(out);
}

// round 3
// speedup vs baseline: 1.6533x; 1.6533x over previous
#include <cuda_runtime.h>

#define N_NODES 100000
#define D 128
#define N_EDGES 400000
#define BN_EPS 1e-5f

#define GEMM_WARPS 8
#define TM 8            // rows per warp
#define WPAD 132        // padded row (words) for transposed W in smem

#define SCAN_T 256
#define SCAN_NB ((N_NODES + SCAN_T - 1) / SCAN_T)   // 391

// Scratch (allocation-free rule: device globals only)
__device__ float g_sum[D];
__device__ float g_sumsq[D];
__device__ float g_scale[D];
__device__ float g_shift[D];
__device__ float g_h[(size_t)N_NODES * D];

// CSR build scratch
__device__ int   g_cnt[N_NODES];       // per-row edge count
__device__ int   g_off[N_NODES + 1];   // exclusive offsets
__device__ int   g_cur[N_NODES];       // scatter cursors
__device__ int   g_scol[N_EDGES];      // row-sorted col indices
__device__ float g_sw[N_EDGES];        // row-sorted weights
__device__ int   g_bsum[SCAN_NB];      // per-block count sums
__device__ int   g_boff[SCAN_NB];      // per-block exclusive offsets

// ---------------------------------------------------------------------------
// K0: zero stat accumulators + histogram counters
// ---------------------------------------------------------------------------
__global__ void k_zero_all() {
    int idx = blockIdx.x * blockDim.x + threadIdx.x;
    for (int i = idx; i < N_NODES; i += gridDim.x * blockDim.x) g_cnt[i] = 0;
    if (idx < D) { g_sum[idx] = 0.f; g_sumsq[idx] = 0.f; }
}

// ---------------------------------------------------------------------------
// K1: per-column sum / sumsq
// ---------------------------------------------------------------------------
__global__ void k_colsum(const float* __restrict__ x) {
    int c = threadIdx.x;
    float s = 0.f, s2 = 0.f;
#pragma unroll 4
    for (int r = blockIdx.x; r < N_NODES; r += gridDim.x) {
        float v = x[(size_t)r * D + c];
        s += v;
        s2 += v * v;
    }
    atomicAdd(&g_sum[c], s);
    atomicAdd(&g_sumsq[c], s2);
}

// ---------------------------------------------------------------------------
// K1b: histogram of destination rows
// ---------------------------------------------------------------------------
__global__ void k_hist(const int* __restrict__ eidx) {
    int e = blockIdx.x * blockDim.x + threadIdx.x;
    if (e < N_EDGES) atomicAdd(&g_cnt[eidx[e]], 1);
}

// ---------------------------------------------------------------------------
// K2: fold BN into per-column scale/shift
// ---------------------------------------------------------------------------
__global__ void k_stats(const float* __restrict__ gamma, const float* __restrict__ beta) {
    int c = threadIdx.x;
    const float inv_n = 1.f / (float)N_NODES;
    float mu = g_sum[c] * inv_n;
    float var = g_sumsq[c] * inv_n - mu * mu;
    float rs = rsqrtf(var + BN_EPS);
    float sc = gamma[c] * rs;
    g_scale[c] = sc;
    g_shift[c] = beta[c] - mu * sc;
}

// ---------------------------------------------------------------------------
// Scan phase A: coalesced per-block sums of g_cnt
// ---------------------------------------------------------------------------
__global__ void k_scan_reduce() {
    int idx = blockIdx.x * SCAN_T + threadIdx.x;
    int v = (idx < N_NODES) ? g_cnt[idx] : 0;
#pragma unroll
    for (int o = 16; o > 0; o >>= 1) v += __shfl_down_sync(0xffffffffu, v, o);
    __shared__ int ws[SCAN_T / 32];
    if ((threadIdx.x & 31) == 0) ws[threadIdx.x >> 5] = v;
    __syncthreads();
    if (threadIdx.x < SCAN_T / 32) {
        int s = ws[threadIdx.x];
#pragma unroll
        for (int o = SCAN_T / 64; o > 0; o >>= 1) s += __shfl_down_sync(0xffu, s, o);
        if (threadIdx.x == 0) g_bsum[blockIdx.x] = s;
    }
}

// ---------------------------------------------------------------------------
// Scan phase B: single block scans SCAN_NB block sums (exclusive)
// ---------------------------------------------------------------------------
__global__ void k_scan_mid() {
    __shared__ int sm[512];
    int t = threadIdx.x;
    sm[t] = (t < SCAN_NB) ? g_bsum[t] : 0;
    __syncthreads();
#pragma unroll
    for (int o = 1; o < 512; o <<= 1) {
        int v = (t >= o) ? sm[t - o] : 0;
        __syncthreads();
        sm[t] += v;
        __syncthreads();
    }
    if (t < SCAN_NB) g_boff[t] = (t == 0) ? 0 : sm[t - 1];
    if (t == 0) g_off[N_NODES] = N_EDGES;   // total is known
}

// ---------------------------------------------------------------------------
// Scan phase C: block-local exclusive scan + block offset -> g_off, g_cur
// ---------------------------------------------------------------------------
__global__ void k_scan_final() {
    __shared__ int sm[SCAN_T];
    int t = threadIdx.x;
    int idx = blockIdx.x * SCAN_T + t;
    int v = (idx < N_NODES) ? g_cnt[idx] : 0;
    sm[t] = v;
    __syncthreads();
#pragma unroll
    for (int o = 1; o < SCAN_T; o <<= 1) {
        int u = (t >= o) ? sm[t - o] : 0;
        __syncthreads();
        sm[t] += u;
        __syncthreads();
    }
    if (idx < N_NODES) {
        int excl = sm[t] - v + g_boff[blockIdx.x];
        g_off[idx] = excl;
        g_cur[idx] = excl;
    }
}

// ---------------------------------------------------------------------------
// K2c: scatter edges into row-sorted CSR arrays
// ---------------------------------------------------------------------------
__global__ void k_scatter(const int* __restrict__ eidx, const float* __restrict__ ew) {
    int e = blockIdx.x * blockDim.x + threadIdx.x;
    if (e >= N_EDGES) return;
    int r = eidx[e];
    int c = eidx[N_EDGES + e];
    int pos = atomicAdd(&g_cur[r], 1);
    g_scol[pos] = c;
    g_sw[pos] = ew[e];
}

// ---------------------------------------------------------------------------
// K3: fused BN -> ReLU -> GEMM (h = y @ W^T), writes g_h and out = h*h.
// ---------------------------------------------------------------------------
extern __shared__ float sm_gemm[];

__global__ void __launch_bounds__(256, 2) k_gemm(const float* __restrict__ x,
                                                 const float* __restrict__ W,
                                                 float* __restrict__ out) {
    float* Wsh = sm_gemm;                       // D * WPAD
    float* ysh = Wsh + D * WPAD;                // GEMM_WARPS * TM * D
    float* ssc = ysh + GEMM_WARPS * TM * D;     // D
    float* ssh = ssc + D;                       // D

    int tid = threadIdx.x;

    for (int i = tid; i < D * D; i += blockDim.x) {
        int j = i / D;
        int k = i - j * D;
        Wsh[k * WPAD + j] = W[i];
    }
    if (tid < D) {
        ssc[tid] = g_scale[tid];
        ssh[tid] = g_shift[tid];
    }
    __syncthreads();

    int warp = tid >> 5;
    int lane = tid & 31;
    float* myY = ysh + warp * TM * D;

    float sc[4], sh[4];
#pragma unroll
    for (int i = 0; i < 4; i++) {
        sc[i] = ssc[4 * lane + i];
        sh[i] = ssh[4 * lane + i];
    }

    const int ntiles = (N_NODES + GEMM_WARPS * TM - 1) / (GEMM_WARPS * TM);
    for (int tile = blockIdx.x; tile < ntiles; tile += gridDim.x) {
        int row0 = tile * (GEMM_WARPS * TM) + warp * TM;

        __syncwarp();
#pragma unroll
        for (int r = 0; r < TM; r++) {
            int row = row0 + r;
            if (row < N_NODES) {
                float4 v = *(const float4*)&x[(size_t)row * D + 4 * lane];
                v.x = fmaxf(0.f, fmaf(v.x, sc[0], sh[0]));
                v.y = fmaxf(0.f, fmaf(v.y, sc[1], sh[1]));
                v.z = fmaxf(0.f, fmaf(v.z, sc[2], sh[2]));
                v.w = fmaxf(0.f, fmaf(v.w, sc[3], sh[3]));
                *(float4*)&myY[r * D + 4 * lane] = v;
            }
        }
        __syncwarp();

        unsigned long long acc[TM][2];
#pragma unroll
        for (int r = 0; r < TM; r++) { acc[r][0] = 0ULL; acc[r][1] = 0ULL; }

#pragma unroll 8
        for (int k = 0; k < D; k++) {
            float4 w4 = *(const float4*)&Wsh[k * WPAD + 4 * lane];
            unsigned long long w01, w23;
            asm("mov.b64 %0, {%1,%2};" : "=l"(w01) : "f"(w4.x), "f"(w4.y));
            asm("mov.b64 %0, {%1,%2};" : "=l"(w23) : "f"(w4.z), "f"(w4.w));
#pragma unroll
            for (int r = 0; r < TM; r++) {
                float yv = myY[r * D + k];
                unsigned long long yy;
                asm("mov.b64 %0, {%1,%1};" : "=l"(yy) : "f"(yv));
                asm("fma.rn.f32x2 %0, %1, %2, %0;" : "+l"(acc[r][0]) : "l"(yy), "l"(w01));
                asm("fma.rn.f32x2 %0, %1, %2, %0;" : "+l"(acc[r][1]) : "l"(yy), "l"(w23));
            }
        }

#pragma unroll
        for (int r = 0; r < TM; r++) {
            int row = row0 + r;
            if (row < N_NODES) {
                float4 hv;
                asm("mov.b64 {%0,%1}, %2;" : "=f"(hv.x), "=f"(hv.y) : "l"(acc[r][0]));
                asm("mov.b64 {%0,%1}, %2;" : "=f"(hv.z), "=f"(hv.w) : "l"(acc[r][1]));
                *(float4*)&g_h[(size_t)row * D + 4 * lane] = hv;
                float4 o = make_float4(hv.x * hv.x, hv.y * hv.y, hv.z * hv.z, hv.w * hv.w);
                *(float4*)&out[(size_t)row * D + 4 * lane] = o;
            }
        }
    }
}

// ---------------------------------------------------------------------------
// K4: CSR aggregation. One warp per node, lanes cover 128 features (4 each).
// ---------------------------------------------------------------------------
__global__ void k_agg(float* __restrict__ out) {
    int warp_global = (int)((blockIdx.x * (unsigned)blockDim.x + threadIdx.x) >> 5);
    int lane = threadIdx.x & 31;
    if (warp_global >= N_NODES) return;
    int n = warp_global;
    int s = g_off[n];
    int e = g_off[n + 1];
    if (s == e) return;   // out already holds h*h

    float4 acc0 = make_float4(0.f, 0.f, 0.f, 0.f);
    float4 acc1 = make_float4(0.f, 0.f, 0.f, 0.f);

    int j = s;
    for (; j + 1 < e; j += 2) {
        int c0 = g_scol[j];
        int c1 = g_scol[j + 1];
        float w0 = g_sw[j];
        float w1 = g_sw[j + 1];
        float4 v0 = *(const float4*)&g_h[(size_t)c0 * D + 4 * lane];
        float4 v1 = *(const float4*)&g_h[(size_t)c1 * D + 4 * lane];
        acc0.x = fmaf(w0, v0.x, acc0.x); acc0.y = fmaf(w0, v0.y, acc0.y);
        acc0.z = fmaf(w0, v0.z, acc0.z); acc0.w = fmaf(w0, v0.w, acc0.w);
        acc1.x = fmaf(w1, v1.x, acc1.x); acc1.y = fmaf(w1, v1.y, acc1.y);
        acc1.z = fmaf(w1, v1.z, acc1.z); acc1.w = fmaf(w1, v1.w, acc1.w);
    }
    if (j < e) {
        int c0 = g_scol[j];
        float w0 = g_sw[j];
        float4 v0 = *(const float4*)&g_h[(size_t)c0 * D + 4 * lane];
        acc0.x = fmaf(w0, v0.x, acc0.x); acc0.y = fmaf(w0, v0.y, acc0.y);
        acc0.z = fmaf(w0, v0.z, acc0.z); acc0.w = fmaf(w0, v0.w, acc0.w);
    }
    acc0.x += acc1.x; acc0.y += acc1.y; acc0.z += acc1.z; acc0.w += acc1.w;

    float4* dst = (float4*)&out[(size_t)n * D + 4 * lane];
    float4 o = *dst;
    o.x += acc0.x; o.y += acc0.y; o.z += acc0.z; o.w += acc0.w;
    *dst = o;
}

// ---------------------------------------------------------------------------
extern "C" void kernel_launch(void* const* d_in, const int* in_sizes, int n_in,
                              void* d_out, int out_size) {
    const float* x     = (const float*)d_in[0];
    const int*   eidx  = (const int*)d_in[1];
    const float* ew    = (const float*)d_in[2];
    const float* gamma = (const float*)d_in[3];
    const float* beta  = (const float*)d_in[4];
    const float* W     = (const float*)d_in[5];
    float* out = (float*)d_out;

    k_zero_all<<<200, 512>>>();
    k_colsum<<<464, D>>>(x);
    k_hist<<<(N_EDGES + 255) / 256, 256>>>(eidx);
    k_stats<<<1, D>>>(gamma, beta);
    k_scan_reduce<<<SCAN_NB, SCAN_T>>>();
    k_scan_mid<<<1, 512>>>();
    k_scan_final<<<SCAN_NB, SCAN_T>>>();
    k_scatter<<<(N_EDGES + 255) / 256, 256>>>(eidx, ew);

    const size_t smem = (size_t)(D * WPAD + GEMM_WARPS * TM * D + 2 * D) * sizeof(float);
    cudaFuncSetAttribute(k_gemm, cudaFuncAttributeMaxDynamicSharedMemorySize, (int)smem);
    k_gemm<<<304, 256, smem>>>(x, W, out);

    k_agg<<<(N_NODES * 32 + 255) / 256, 256>>>(out);
}

// round 4
// speedup vs baseline: 2.3194x; 1.4029x over previous
#include <cuda_runtime.h>

#define N_NODES 100000
#define D 128
#define N_EDGES 400000
#define BN_EPS 1e-5f

#define GEMM_WARPS 8
#define TM 8            // rows per warp
#define WPAD 132        // padded row (words) for transposed W in smem

#define ELLW 32         // padded edges per node (P(deg>32) ~ 1e-16 for Poisson(4))
#define OVF_MAX 8192

#define CS_BLOCKS 1184
#define CS_T 256

// Scratch (allocation-free rule: device globals only)
__device__ float g_sum[D];
__device__ float g_sumsq[D];
__device__ float g_h[(size_t)N_NODES * D];

__device__ int   g_cnt[N_NODES];                    // per-row edge count / cursor
__device__ int2  g_ell[(size_t)N_NODES * ELLW];     // {col, weight-bits}
__device__ int   g_ovf_n;
__device__ int2  g_ovf[OVF_MAX];                    // {row, col}
__device__ float g_ovf_w[OVF_MAX];

// ---------------------------------------------------------------------------
// K0: zero accumulators + ELL counters
// ---------------------------------------------------------------------------
__global__ void k_zero_all() {
    int idx = blockIdx.x * blockDim.x + threadIdx.x;
    for (int i = idx; i < N_NODES; i += gridDim.x * blockDim.x) g_cnt[i] = 0;
    if (idx < D) { g_sum[idx] = 0.f; g_sumsq[idx] = 0.f; }
    if (idx == 0) g_ovf_n = 0;
}

// ---------------------------------------------------------------------------
// K1: column sums via full-occupancy float4 grid-stride.
// Stride (CS_BLOCKS*CS_T) is a multiple of 32 float4s => each thread owns a
// fixed group of 4 columns: c0 = (gtid % 32) * 4.
// ---------------------------------------------------------------------------
__global__ void __launch_bounds__(CS_T) k_colsum(const float4* __restrict__ x4) {
    const int N4 = N_NODES * D / 4;   // 3,200,000
    int gtid = blockIdx.x * CS_T + threadIdx.x;

    float s0 = 0.f, s1 = 0.f, s2 = 0.f, s3 = 0.f;
    float q0 = 0.f, q1 = 0.f, q2 = 0.f, q3 = 0.f;
#pragma unroll 4
    for (int i = gtid; i < N4; i += CS_BLOCKS * CS_T) {
        float4 v = __ldg(&x4[i]);
        s0 += v.x; q0 += v.x * v.x;
        s1 += v.y; q1 += v.y * v.y;
        s2 += v.z; q2 += v.z * v.z;
        s3 += v.w; q3 += v.w * v.w;
    }

    __shared__ float ss[D];
    __shared__ float sq[D];
    int t = threadIdx.x;
    if (t < D) { ss[t] = 0.f; sq[t] = 0.f; }
    __syncthreads();

    int c0 = (gtid & 31) * 4;
    atomicAdd(&ss[c0 + 0], s0); atomicAdd(&sq[c0 + 0], q0);
    atomicAdd(&ss[c0 + 1], s1); atomicAdd(&sq[c0 + 1], q1);
    atomicAdd(&ss[c0 + 2], s2); atomicAdd(&sq[c0 + 2], q2);
    atomicAdd(&ss[c0 + 3], s3); atomicAdd(&sq[c0 + 3], q3);
    __syncthreads();

    if (t < D) {
        atomicAdd(&g_sum[t], ss[t]);
        atomicAdd(&g_sumsq[t], sq[t]);
    }
}

// ---------------------------------------------------------------------------
// K2: build padded ELL adjacency in one pass (atomic cursor per row)
// ---------------------------------------------------------------------------
__global__ void k_build(const int* __restrict__ eidx, const float* __restrict__ ew) {
    int e = blockIdx.x * blockDim.x + threadIdx.x;
    if (e >= N_EDGES) return;
    int r = eidx[e];
    int c = eidx[N_EDGES + e];
    float w = ew[e];
    int pos = atomicAdd(&g_cnt[r], 1);
    if (pos < ELLW) {
        g_ell[(size_t)r * ELLW + pos] = make_int2(c, __float_as_int(w));
    } else {
        int o = atomicAdd(&g_ovf_n, 1);
        if (o < OVF_MAX) { g_ovf[o] = make_int2(r, c); g_ovf_w[o] = w; }
    }
}

// ---------------------------------------------------------------------------
// K3: fused stats -> BN -> ReLU -> GEMM (h = y @ W^T), out = h*h.
// Per-block stats derivation from g_sum/g_sumsq (replaces separate kernel).
// ---------------------------------------------------------------------------
extern __shared__ float sm_gemm[];

__global__ void __launch_bounds__(256, 2) k_gemm(const float* __restrict__ x,
                                                 const float* __restrict__ W,
                                                 const float* __restrict__ gamma,
                                                 const float* __restrict__ beta,
                                                 float* __restrict__ out) {
    float* Wsh = sm_gemm;                       // D * WPAD
    float* ysh = Wsh + D * WPAD;                // GEMM_WARPS * TM * D
    float* ssc = ysh + GEMM_WARPS * TM * D;     // D
    float* ssh = ssc + D;                       // D

    int tid = threadIdx.x;

    for (int i = tid; i < D * D; i += blockDim.x) {
        int j = i / D;
        int k = i - j * D;
        Wsh[k * WPAD + j] = W[i];
    }
    if (tid < D) {
        const float inv_n = 1.f / (float)N_NODES;
        float mu = g_sum[tid] * inv_n;
        float var = g_sumsq[tid] * inv_n - mu * mu;
        float rs = rsqrtf(var + BN_EPS);
        float sc = gamma[tid] * rs;
        ssc[tid] = sc;
        ssh[tid] = beta[tid] - mu * sc;
    }
    __syncthreads();

    int warp = tid >> 5;
    int lane = tid & 31;
    float* myY = ysh + warp * TM * D;

    float sc[4], sh[4];
#pragma unroll
    for (int i = 0; i < 4; i++) {
        sc[i] = ssc[4 * lane + i];
        sh[i] = ssh[4 * lane + i];
    }

    const int ntiles = (N_NODES + GEMM_WARPS * TM - 1) / (GEMM_WARPS * TM);
    for (int tile = blockIdx.x; tile < ntiles; tile += gridDim.x) {
        int row0 = tile * (GEMM_WARPS * TM) + warp * TM;

        __syncwarp();
#pragma unroll
        for (int r = 0; r < TM; r++) {
            int row = row0 + r;
            if (row < N_NODES) {
                float4 v = *(const float4*)&x[(size_t)row * D + 4 * lane];
                v.x = fmaxf(0.f, fmaf(v.x, sc[0], sh[0]));
                v.y = fmaxf(0.f, fmaf(v.y, sc[1], sh[1]));
                v.z = fmaxf(0.f, fmaf(v.z, sc[2], sh[2]));
                v.w = fmaxf(0.f, fmaf(v.w, sc[3], sh[3]));
                *(float4*)&myY[r * D + 4 * lane] = v;
            }
        }
        __syncwarp();

        unsigned long long acc[TM][2];
#pragma unroll
        for (int r = 0; r < TM; r++) { acc[r][0] = 0ULL; acc[r][1] = 0ULL; }

#pragma unroll 8
        for (int k = 0; k < D; k++) {
            float4 w4 = *(const float4*)&Wsh[k * WPAD + 4 * lane];
            unsigned long long w01, w23;
            asm("mov.b64 %0, {%1,%2};" : "=l"(w01) : "f"(w4.x), "f"(w4.y));
            asm("mov.b64 %0, {%1,%2};" : "=l"(w23) : "f"(w4.z), "f"(w4.w));
#pragma unroll
            for (int r = 0; r < TM; r++) {
                float yv = myY[r * D + k];
                unsigned long long yy;
                asm("mov.b64 %0, {%1,%1};" : "=l"(yy) : "f"(yv));
                asm("fma.rn.f32x2 %0, %1, %2, %0;" : "+l"(acc[r][0]) : "l"(yy), "l"(w01));
                asm("fma.rn.f32x2 %0, %1, %2, %0;" : "+l"(acc[r][1]) : "l"(yy), "l"(w23));
            }
        }

#pragma unroll
        for (int r = 0; r < TM; r++) {
            int row = row0 + r;
            if (row < N_NODES) {
                float4 hv;
                asm("mov.b64 {%0,%1}, %2;" : "=f"(hv.x), "=f"(hv.y) : "l"(acc[r][0]));
                asm("mov.b64 {%0,%1}, %2;" : "=f"(hv.z), "=f"(hv.w) : "l"(acc[r][1]));
                *(float4*)&g_h[(size_t)row * D + 4 * lane] = hv;
                float4 o = make_float4(hv.x * hv.x, hv.y * hv.y, hv.z * hv.z, hv.w * hv.w);
                *(float4*)&out[(size_t)row * D + 4 * lane] = o;
            }
        }
    }
}

// ---------------------------------------------------------------------------
// K4: ELL aggregation. One warp per node; lanes cover 128 features (4 each).
// No atomics; 4-way unroll for gather MLP.
// ---------------------------------------------------------------------------
__global__ void k_agg(float* __restrict__ out) {
    int n = (int)((blockIdx.x * (unsigned)blockDim.x + threadIdx.x) >> 5);
    int lane = threadIdx.x & 31;
    if (n >= N_NODES) return;
    int cnt = g_cnt[n];
    int m = cnt < ELLW ? cnt : ELLW;
    if (m == 0) return;   // out already holds h*h

    const int2* row = &g_ell[(size_t)n * ELLW];

    float4 a0 = make_float4(0.f, 0.f, 0.f, 0.f);
    float4 a1 = make_float4(0.f, 0.f, 0.f, 0.f);
    float4 a2 = make_float4(0.f, 0.f, 0.f, 0.f);
    float4 a3 = make_float4(0.f, 0.f, 0.f, 0.f);

    int j = 0;
    for (; j + 3 < m; j += 4) {
        int2 e0 = row[j], e1 = row[j + 1], e2 = row[j + 2], e3 = row[j + 3];
        float4 v0 = *(const float4*)&g_h[(size_t)e0.x * D + 4 * lane];
        float4 v1 = *(const float4*)&g_h[(size_t)e1.x * D + 4 * lane];
        float4 v2 = *(const float4*)&g_h[(size_t)e2.x * D + 4 * lane];
        float4 v3 = *(const float4*)&g_h[(size_t)e3.x * D + 4 * lane];
        float w0 = __int_as_float(e0.y), w1 = __int_as_float(e1.y);
        float w2 = __int_as_float(e2.y), w3 = __int_as_float(e3.y);
        a0.x = fmaf(w0, v0.x, a0.x); a0.y = fmaf(w0, v0.y, a0.y);
        a0.z = fmaf(w0, v0.z, a0.z); a0.w = fmaf(w0, v0.w, a0.w);
        a1.x = fmaf(w1, v1.x, a1.x); a1.y = fmaf(w1, v1.y, a1.y);
        a1.z = fmaf(w1, v1.z, a1.z); a1.w = fmaf(w1, v1.w, a1.w);
        a2.x = fmaf(w2, v2.x, a2.x); a2.y = fmaf(w2, v2.y, a2.y);
        a2.z = fmaf(w2, v2.z, a2.z); a2.w = fmaf(w2, v2.w, a2.w);
        a3.x = fmaf(w3, v3.x, a3.x); a3.y = fmaf(w3, v3.y, a3.y);
        a3.z = fmaf(w3, v3.z, a3.z); a3.w = fmaf(w3, v3.w, a3.w);
    }
    for (; j < m; j++) {
        int2 e0 = row[j];
        float w0 = __int_as_float(e0.y);
        float4 v0 = *(const float4*)&g_h[(size_t)e0.x * D + 4 * lane];
        a0.x = fmaf(w0, v0.x, a0.x); a0.y = fmaf(w0, v0.y, a0.y);
        a0.z = fmaf(w0, v0.z, a0.z); a0.w = fmaf(w0, v0.w, a0.w);
    }
    a0.x += a1.x + a2.x + a3.x;
    a0.y += a1.y + a2.y + a3.y;
    a0.z += a1.z + a2.z + a3.z;
    a0.w += a1.w + a2.w + a3.w;

    float4* dst = (float4*)&out[(size_t)n * D + 4 * lane];
    float4 o = *dst;
    o.x += a0.x; o.y += a0.y; o.z += a0.z; o.w += a0.w;
    *dst = o;
}

// ---------------------------------------------------------------------------
// K5: drain overflow edges (normally zero). Single warp, serial, runs after
// k_agg so plain RMW is race-free.
// ---------------------------------------------------------------------------
__global__ void k_ovf(float* __restrict__ out) {
    if (threadIdx.x >= 32) return;
    int lane = threadIdx.x;
    int n = g_ovf_n;
    if (n > OVF_MAX) n = OVF_MAX;
    for (int i = 0; i < n; i++) {
        int2 rc = g_ovf[i];
        float w = g_ovf_w[i];
        float4 v = *(const float4*)&g_h[(size_t)rc.y * D + 4 * lane];
        float4* dst = (float4*)&out[(size_t)rc.x * D + 4 * lane];
        float4 o = *dst;
        o.x = fmaf(w, v.x, o.x); o.y = fmaf(w, v.y, o.y);
        o.z = fmaf(w, v.z, o.z); o.w = fmaf(w, v.w, o.w);
        *dst = o;
    }
}

// ---------------------------------------------------------------------------
extern "C" void kernel_launch(void* const* d_in, const int* in_sizes, int n_in,
                              void* d_out, int out_size) {
    const float* x     = (const float*)d_in[0];
    const int*   eidx  = (const int*)d_in[1];
    const float* ew    = (const float*)d_in[2];
    const float* gamma = (const float*)d_in[3];
    const float* beta  = (const float*)d_in[4];
    const float* W     = (const float*)d_in[5];
    float* out = (float*)d_out;

    k_zero_all<<<200, 512>>>();
    k_colsum<<<CS_BLOCKS, CS_T>>>((const float4*)x);
    k_build<<<(N_EDGES + 255) / 256, 256>>>(eidx, ew);

    const size_t smem = (size_t)(D * WPAD + GEMM_WARPS * TM * D + 2 * D) * sizeof(float);
    cudaFuncSetAttribute(k_gemm, cudaFuncAttributeMaxDynamicSharedMemorySize, (int)smem);
    k_gemm<<<304, 256, smem>>>(x, W, gamma, beta, out);

    k_agg<<<(N_NODES * 32 + 255) / 256, 256>>>(out);
    k_ovf<<<1, 32>>>(out);
}